// round 6
// baseline (speedup 1.0000x reference)
#include <cuda_runtime.h>

#define B_    128
#define H_    512
#define HG_   2048   // 4*H
#define T_    512
#define FIN   64
#define FOUT  8
#define WOUT  64
#define KT    32
#define NCTA  128
#define NTHR  512

// dynamic smem layout
#define SAT_FLOATS (KT*32)                 // 1024 floats = 4KB per A tile
#define SW_STRIDE  36                      // padded row stride (floats)
#define SW_FLOATS  (64*SW_STRIDE)          // 2304 floats = 9216B per W tile
#define SMEM_W_OFF   (8*SAT_FLOATS*4)                  // 32768
#define SMEM_RED_OFF (SMEM_W_OFF + 8*SW_FLOATS*4)      // 106496
#define SMEM_TOTAL   (SMEM_RED_OFF + 4*64*17*8)        // 141312

// persistent device state (allocation-free)
__device__ float g_h[2][3][B_][H_];   // double-buffered hidden state
__device__ float g_c[3][B_][H_];      // cell state
__device__ float g_pred[B_][FOUT];    // decoder feedback
__device__ float g_xT[T_][B_][FIN];   // pre-transposed input
__device__ unsigned g_cnt = 0;
__device__ volatile unsigned g_gen = 0;

typedef unsigned long long u64;

__device__ __forceinline__ u64 pack2(float a) {
    u64 r; asm("mov.b64 %0, {%1, %1};" : "=l"(r) : "f"(a)); return r;
}
__device__ __forceinline__ void fma2(u64& acc, u64 w, u64 a) {
    asm("fma.rn.f32x2 %0, %1, %2, %0;" : "+l"(acc) : "l"(w), "l"(a));
}
__device__ __forceinline__ float sigmoidf_(float x) { return 1.f / (1.f + expf(-x)); }

// grid-wide sense-reversing barrier; 128 CTAs co-resident (one wave).
// __threadfence = fence.gpu => CCTL.IVALL: publishes stores + invalidates L1D.
__device__ __forceinline__ void grid_barrier() {
    __syncthreads();
    if (threadIdx.x == 0) {
        __threadfence();
        unsigned gen = g_gen;
        if (atomicAdd(&g_cnt, 1u) == NCTA - 1) {
            g_cnt = 0;
            __threadfence();
            g_gen = gen + 1;
        } else {
            while (g_gen == gen) {}
        }
        __threadfence();
    }
    __syncthreads();
}

// per-K-group barrier (128 threads), ids 1..4 (0 is __syncthreads)
__device__ __forceinline__ void group_bar(int gk) {
    asm volatile("bar.sync %0, 128;" :: "r"(gk + 1) : "memory");
}

// ---------------------------------------------------------------------------
// One fused LSTM layer-step: gates = A1@W1^T + h_prev@W2^T + bi + bh -> cell.
// CTA tile: 32 b x 16 j x 4 quadrants. 512 thr = 4 K-groups x 4 b-warps.
// Per lane: 8 b (4 packed pairs) x 2 gates (ln, ln+32) -> 8 f32x2 accs.
// ---------------------------------------------------------------------------
__device__ __noinline__ void layer_step(
    char* smem, int tid,
    const float* A1, int a1s, int K1,
    const float* W1, const float* W2,
    const float* bi, const float* bh,
    int l, int np, int j0, int b0)
{
    const int gk = tid >> 7;        // K-group 0..3
    const int wt = tid & 127;
    const int ln = wt & 31;         // lane -> gate rows ln, ln+32
    const int bg = wt >> 5;         // b-group (8 rows each)
    const float* A2 = &g_h[np ^ 1][l][0][0];

    float* sA[2] = { (float*)smem + (gk*2+0)*SAT_FLOATS,
                     (float*)smem + (gk*2+1)*SAT_FLOATS };
    float* sW[2] = { (float*)(smem + SMEM_W_OFF) + (gk*2+0)*SW_FLOATS,
                     (float*)(smem + SMEM_W_OFF) + (gk*2+1)*SW_FLOATS };

    const int nT1 = (K1 + KT - 1) / KT;
    const int nT  = nT1 + H_/KT;                 // total k-tiles
    const int myN = (nT - gk + 3) >> 2;          // my round-robin share

    u64 acc[8] = {0,0,0,0,0,0,0,0};

    auto load_tile = [&](int ti, float* dA, float* dW) {
        const float* A; const float* W; int ars, wK, k0, kt;
        if (ti < nT1) { A = A1; W = W1; ars = a1s; wK = K1; k0 = ti*KT;
                        kt = (K1 - k0 < KT) ? (K1 - k0) : KT; }
        else          { A = A2; W = W2; ars = H_;  wK = H_;  k0 = (ti-nT1)*KT; kt = KT; }
        // A tile -> transposed store sAT[k][b] (zero-pad k>=kt)
        #pragma unroll
        for (int r = 0; r < 2; r++) {
            int k4 = bg + r*4;
            float4 v = make_float4(0.f,0.f,0.f,0.f);
            if (k4*4 < kt)
                v = *(const float4*)(A + (size_t)(b0+ln)*ars + k0 + k4*4);
            dA[(k4*4+0)*32 + ln] = v.x;
            dA[(k4*4+1)*32 + ln] = v.y;
            dA[(k4*4+2)*32 + ln] = v.z;
            dA[(k4*4+3)*32 + ln] = v.w;
        }
        // W tile: 64 gate rows x kt, padded stride 36
        #pragma unroll
        for (int r = 0; r < 4; r++) {
            int idx = wt + r*128;
            int g = idx >> 3, k4 = idx & 7;
            int n = (g >> 4)*H_ + j0 + (g & 15);
            float4 v = make_float4(0.f,0.f,0.f,0.f);
            if (k4*4 < kt)
                v = *(const float4*)(W + (size_t)n*wK + k0 + k4*4);
            *(float4*)(dW + g*SW_STRIDE + k4*4) = v;
        }
    };

    load_tile(gk, sA[0], sW[0]);
    group_bar(gk);

    for (int r = 0; r < myN; r++) {
        const float* cA = sA[r & 1];
        const float* cW = sW[r & 1];
        if (r + 1 < myN) load_tile(gk + (r+1)*4, sA[(r+1)&1], sW[(r+1)&1]);

        const float* wr1 = cW + ln*SW_STRIDE;
        const float* wr2 = cW + (ln+32)*SW_STRIDE;
        const float* ar  = cA + bg*8;
        #pragma unroll 4
        for (int kk = 0; kk < KT; kk += 4) {
            float4 w1 = *(const float4*)(wr1 + kk);
            float4 w2 = *(const float4*)(wr2 + kk);
            u64 W1p[4] = {pack2(w1.x), pack2(w1.y), pack2(w1.z), pack2(w1.w)};
            u64 W2p[4] = {pack2(w2.x), pack2(w2.y), pack2(w2.z), pack2(w2.w)};
            #pragma unroll
            for (int k = 0; k < 4; k++) {
                ulonglong2 aA = *(const ulonglong2*)(ar + (kk+k)*32);
                ulonglong2 aB = *(const ulonglong2*)(ar + (kk+k)*32 + 4);
                fma2(acc[0], W1p[k], aA.x);
                fma2(acc[1], W1p[k], aA.y);
                fma2(acc[2], W1p[k], aB.x);
                fma2(acc[3], W1p[k], aB.y);
                fma2(acc[4], W2p[k], aA.x);
                fma2(acc[5], W2p[k], aA.y);
                fma2(acc[6], W2p[k], aB.x);
                fma2(acc[7], W2p[k], aB.y);
            }
        }
        group_bar(gk);
    }

    // cross-K-group reduction via smem (padded to kill bank conflicts)
    u64* red = (u64*)(smem + SMEM_RED_OFF);
    u64* rg  = red + (size_t)gk*64*17;
    #pragma unroll
    for (int bp = 0; bp < 4; bp++) {
        rg[ln*17      + bg*4 + bp] = acc[bp];
        rg[(ln+32)*17 + bg*4 + bp] = acc[4+bp];
    }
    __syncthreads();

    // cell phase: thread -> (b_l = tid>>4, j_l = tid&15); coalesced h/c I/O
    {
        const float* redf = (const float*)red;
        int j_l = tid & 15;
        int b_l = tid >> 4;
        int bp = b_l >> 1, half = b_l & 1;
        float gate[4];
        #pragma unroll
        for (int q = 0; q < 4; q++) {
            int g = q*16 + j_l;
            float s = 0.f;
            #pragma unroll
            for (int gg = 0; gg < 4; gg++)
                s += redf[((gg*64 + g)*17 + bp)*2 + half];
            int n = q*H_ + j0 + j_l;
            gate[q] = s + bi[n] + bh[n];
        }
        int b = b0 + b_l, j = j0 + j_l;
        float co = g_c[l][b][j];
        float cn = sigmoidf_(gate[1]) * co + sigmoidf_(gate[0]) * tanhf(gate[2]);
        g_c[l][b][j] = cn;
        g_h[np][l][b][j] = sigmoidf_(gate[3]) * tanhf(cn);
    }
}

// ---------------------------------------------------------------------------
__global__ __launch_bounds__(NTHR, 1) void lstm_persist(
    const float* __restrict__ x,
    const float* __restrict__ eWih0, const float* __restrict__ eWih,
    const float* __restrict__ eWhh,  const float* __restrict__ ebih,
    const float* __restrict__ ebhh,
    const float* __restrict__ dWih0, const float* __restrict__ dWih,
    const float* __restrict__ dWhh,  const float* __restrict__ dbih,
    const float* __restrict__ dbhh,
    const float* __restrict__ fcw,   const float* __restrict__ fcb,
    float* __restrict__ out)
{
    extern __shared__ char smem[];
    const int tid = threadIdx.x;
    const int j0  = (blockIdx.x & 31) * 16;
    const int b0  = (blockIdx.x >> 5) * 32;

    // ---- init: zero h/c, seed decoder input, pre-transpose x ----
    {
        int gid = blockIdx.x * NTHR + tid;
        #pragma unroll
        for (int r = 0; r < 3; r++) {
            int idx = gid + r * (NCTA * NTHR);
            (&g_h[0][0][0][0])[idx] = 0.f;
            (&g_c[0][0][0])[idx]    = 0.f;
        }
        if (gid < B_ * FOUT) {
            int b = gid >> 3, f = gid & 7;
            g_pred[b][f] = x[(size_t)b * (FIN * T_) + (size_t)(FIN - 1) * T_ + f];
        }
        for (int i = gid; i < T_ * B_ * FIN; i += NCTA * NTHR) {
            int t = i >> 13, rem = i & 8191;
            int b = rem >> 6, k = rem & 63;
            (&g_xT[0][0][0])[i] = x[(size_t)b * (FIN * T_) + (size_t)k * T_ + t];
        }
    }
    grid_barrier();

    const int WS = HG_ * H_;
    int s = 0;

    // ---- encoder ----
    for (int t = 0; t < T_; ++t, ++s) {
        int np = (s & 1) ^ 1;
        layer_step(smem, tid, &g_xT[t][0][0], FIN, FIN,
                   eWih0, eWhh, ebih, ebhh, 0, np, j0, b0);
        grid_barrier();
        layer_step(smem, tid, &g_h[np][0][0][0], H_, H_,
                   eWih, eWhh + WS, ebih + HG_, ebhh + HG_, 1, np, j0, b0);
        grid_barrier();
        layer_step(smem, tid, &g_h[np][1][0][0], H_, H_,
                   eWih + WS, eWhh + 2*WS, ebih + 2*HG_, ebhh + 2*HG_, 2, np, j0, b0);
        grid_barrier();
    }

    // ---- decoder ----
    for (int d = 0; d < WOUT; ++d, ++s) {
        int np = (s & 1) ^ 1;
        layer_step(smem, tid, &g_pred[0][0], FOUT, FOUT,
                   dWih0, dWhh, dbih, dbhh, 0, np, j0, b0);
        grid_barrier();
        layer_step(smem, tid, &g_h[np][0][0][0], H_, H_,
                   dWih, dWhh + WS, dbih + HG_, dbhh + HG_, 1, np, j0, b0);
        grid_barrier();
        layer_step(smem, tid, &g_h[np][1][0][0], H_, H_,
                   dWih + WS, dWhh + 2*WS, dbih + 2*HG_, dbhh + 2*HG_, 2, np, j0, b0);
        grid_barrier();

        if (tid < 256) {   // FC head: CTA = batch row b = blockIdx.x
            int f = tid >> 5, lnn = tid & 31, b = blockIdx.x;
            const float* hrow = &g_h[np][2][b][0];
            const float* wrow = fcw + f * H_;
            float ssum = 0.f;
            #pragma unroll 4
            for (int j = lnn; j < H_; j += 32) ssum += hrow[j] * wrow[j];
            #pragma unroll
            for (int o = 16; o; o >>= 1) ssum += __shfl_down_sync(0xffffffffu, ssum, o);
            if (lnn == 0) {
                float v = ssum + fcb[f];
                g_pred[b][f] = v;
                out[(size_t)b * (FOUT * WOUT) + f * WOUT + d] = v;
            }
        }
        grid_barrier();
    }
}

// ---------------------------------------------------------------------------
extern "C" void kernel_launch(void* const* d_in, const int* in_sizes, int n_in,
                              void* d_out, int out_size)
{
    const float* x     = (const float*)d_in[0];
    const float* eWih0 = (const float*)d_in[1];
    const float* eWih  = (const float*)d_in[2];
    const float* eWhh  = (const float*)d_in[3];
    const float* ebih  = (const float*)d_in[4];
    const float* ebhh  = (const float*)d_in[5];
    const float* dWih0 = (const float*)d_in[6];
    const float* dWih  = (const float*)d_in[7];
    const float* dWhh  = (const float*)d_in[8];
    const float* dbih  = (const float*)d_in[9];
    const float* dbhh  = (const float*)d_in[10];
    const float* fcw   = (const float*)d_in[11];
    const float* fcb   = (const float*)d_in[12];
    float* out = (float*)d_out;

    cudaFuncSetAttribute(lstm_persist,
                         cudaFuncAttributeMaxDynamicSharedMemorySize, SMEM_TOTAL);
    lstm_persist<<<NCTA, NTHR, SMEM_TOTAL>>>(
        x, eWih0, eWih, eWhh, ebih, ebhh,
        dWih0, dWih, dWhh, dbih, dbhh, fcw, fcb, out);
}

// round 7
// speedup vs baseline: 2.3026x; 2.3026x over previous
#include <cuda_runtime.h>
#include <cuda_bf16.h>

#define B_ 128
#define H_ 512
#define HG_ 2048
#define T_ 512
#define FIN 64
#define FOUT 8
#define WOUT 64
#define NCTA 128
#define NTHR 512
#define NTOT (NCTA*NTHR)

// packed fragment buffers: W[(ntile*NK16+k16)*32+lane] = {b0h,b1h,b0l,b1l}
// A[((mtile*nk+k16)*32+lane)*2 + {0hi,1lo}] = {a0,a1,a2,a3}
__device__ __align__(16) uint4 gWp[6][524288];
__device__ __align__(16) uint4 gXp[1048576];
__device__ __align__(16) uint4 gPh[2][3][16384];
__device__ __align__(16) uint4 gPp[512];
__device__ float gBias[6][HG_];
__device__ float g_h[2][3][B_][H_];
__device__ float g_c[3][B_][H_];
__device__ unsigned g_cnt = 0;
__device__ volatile unsigned g_gen = 0;

__device__ __forceinline__ float sigmoidf_(float x){ return 1.f/(1.f+expf(-x)); }
__device__ __forceinline__ void bsplit(float v, unsigned short& h, unsigned short& l){
    __nv_bfloat16 bh = __float2bfloat16(v);
    __nv_bfloat16 bl = __float2bfloat16(v - __bfloat162float(bh));
    h = __bfloat16_as_ushort(bh); l = __bfloat16_as_ushort(bl);
}
__device__ __forceinline__ unsigned packu(unsigned short e, unsigned short o){
    return (unsigned)e | ((unsigned)o << 16);
}
__device__ __forceinline__ void grid_barrier(){
    __syncthreads();
    if (threadIdx.x == 0){
        __threadfence();
        unsigned gen = g_gen;
        if (atomicAdd(&g_cnt,1u) == NCTA-1){ g_cnt = 0; __threadfence(); g_gen = gen+1; }
        else { while (g_gen == gen) {} }
        __threadfence();
    }
    __syncthreads();
}
__device__ __forceinline__ void mma_bf16(float* d, const uint4 a, unsigned b0, unsigned b1){
    asm volatile("mma.sync.aligned.m16n8k16.row.col.f32.bf16.bf16.f32 "
        "{%0,%1,%2,%3}, {%4,%5,%6,%7}, {%8,%9}, {%0,%1,%2,%3};"
        : "+f"(d[0]), "+f"(d[1]), "+f"(d[2]), "+f"(d[3])
        : "r"(a.x), "r"(a.y), "r"(a.z), "r"(a.w), "r"(b0), "r"(b1));
}

// fused layer-step: CTA tile 32b x 16j x 4 quadrants; 16 warps = 4 Kgroups x (2mw x 2jh)
__device__ __noinline__ void layer_step(
    float* sred, int tid,
    const uint4* __restrict__ pA1, int nk1, const uint4* __restrict__ pA2,
    const uint4* __restrict__ pW, const float* __restrict__ bias,
    int l, int np, int j0, int bt)
{
    const int wid = tid>>5, lane = tid&31;
    const int kg = wid>>2, sub = wid&3, mw = sub&1, jh = sub>>1;
    const int NK16 = nk1 + 32;
    const int mtile = bt*2 + mw;
    const int g = lane>>2;

    const uint4* wp0 = pW + ((size_t)(0*64 + (j0>>3) + jh)*NK16 + kg)*32 + lane;
    const uint4* wp1 = pW + ((size_t)(1*64 + (j0>>3) + jh)*NK16 + kg)*32 + lane;
    const uint4* wp2 = pW + ((size_t)(2*64 + (j0>>3) + jh)*NK16 + kg)*32 + lane;
    const uint4* wp3 = pW + ((size_t)(3*64 + (j0>>3) + jh)*NK16 + kg)*32 + lane;

    float acc[4][4];
    #pragma unroll
    for (int q = 0; q < 4; q++){ acc[q][0]=acc[q][1]=acc[q][2]=acc[q][3]=0.f; }

    auto aptr = [&](int i) -> const uint4* {
        return (i < nk1) ? pA1 + ((size_t)(mtile*nk1 + i)*32 + lane)*2
                         : pA2 + ((size_t)(mtile*32 + (i-nk1))*32 + lane)*2;
    };

    uint4 ahi, alo, w0, w1, w2, w3;
    { const uint4* ap = aptr(kg); ahi = ap[0]; alo = ap[1];
      w0 = *wp0; w1 = *wp1; w2 = *wp2; w3 = *wp3; }

    for (int i = kg; i < NK16; i += 4){
        uint4 nahi, nalo, nw0, nw1, nw2, nw3;
        if (i + 4 < NK16){
            const uint4* ap = aptr(i+4);
            nahi = ap[0]; nalo = ap[1];
            nw0 = wp0[128]; nw1 = wp1[128]; nw2 = wp2[128]; nw3 = wp3[128];
        }
        mma_bf16(acc[0], ahi, w0.x, w0.y);
        mma_bf16(acc[1], ahi, w1.x, w1.y);
        mma_bf16(acc[2], ahi, w2.x, w2.y);
        mma_bf16(acc[3], ahi, w3.x, w3.y);
        mma_bf16(acc[0], ahi, w0.z, w0.w);
        mma_bf16(acc[1], ahi, w1.z, w1.w);
        mma_bf16(acc[2], ahi, w2.z, w2.w);
        mma_bf16(acc[3], ahi, w3.z, w3.w);
        mma_bf16(acc[0], alo, w0.x, w0.y);
        mma_bf16(acc[1], alo, w1.x, w1.y);
        mma_bf16(acc[2], alo, w2.x, w2.y);
        mma_bf16(acc[3], alo, w3.x, w3.y);
        wp0 += 128; wp1 += 128; wp2 += 128; wp3 += 128;
        ahi = nahi; alo = nalo; w0 = nw0; w1 = nw1; w2 = nw2; w3 = nw3;
    }

    {   // partial D -> sred[kg][q*16+jl][b_l], stride 36 (conflict-free)
        const int tig = lane & 3;
        float* rg = sred + kg*2304;
        #pragma unroll
        for (int q = 0; q < 4; q++){
            float* t0 = rg + (q*16 + jh*8 + 2*tig)*36 + mw*16;
            t0[g] = acc[q][0]; t0[g+8] = acc[q][2];
            t0[36+g] = acc[q][1]; t0[36+g+8] = acc[q][3];
        }
    }
    __syncthreads();

    {   // cell phase: thread -> (b_l = tid>>4, j_l = tid&15)
        const int b_l = tid>>4, j_l = tid&15;
        float gate[4];
        #pragma unroll
        for (int q = 0; q < 4; q++){
            float s = 0.f;
            #pragma unroll
            for (int kk = 0; kk < 4; kk++) s += sred[kk*2304 + (q*16+j_l)*36 + b_l];
            gate[q] = s + bias[q*H_ + j0 + j_l];
        }
        const int b = bt*32 + b_l, j = j0 + j_l;
        float co = g_c[l][b][j];
        float cn = sigmoidf_(gate[1])*co + sigmoidf_(gate[0])*tanhf(gate[2]);
        g_c[l][b][j] = cn;
        float hv = sigmoidf_(gate[3])*tanhf(cn);
        g_h[np][l][b][j] = hv;
        // scatter into packed-A fragment slot
        unsigned short hs, ls; bsplit(hv, hs, ls);
        int mt = b>>4, rb = b&15, gg = rb&7, a01 = rb>>3;
        int k16 = j>>4, kr = j&15, tg = (kr>>1)&3, r24 = kr>>3, half = kr&1;
        int regidx = a01 + (r24<<1);
        unsigned short* dst = (unsigned short*)
            (&gPh[np][l][0] + ((size_t)(mt*32 + k16)*32 + (gg*4 + tg))*2);
        dst[regidx*2 + half] = hs;
        dst[8 + regidx*2 + half] = ls;
    }
}

__global__ __launch_bounds__(NTHR, 1) void lstm_persist(
    const float* __restrict__ x,
    const float* __restrict__ eWih0, const float* __restrict__ eWih,
    const float* __restrict__ eWhh,  const float* __restrict__ ebih,
    const float* __restrict__ ebhh,
    const float* __restrict__ dWih0, const float* __restrict__ dWih,
    const float* __restrict__ dWhh,  const float* __restrict__ dbih,
    const float* __restrict__ dbhh,
    const float* __restrict__ fcw,   const float* __restrict__ fcb,
    float* __restrict__ out)
{
    __shared__ float sred[4*2304];
    const int tid = threadIdx.x;
    const int bt = blockIdx.x >> 5;
    const int j0 = (blockIdx.x & 31)*16;
    const int gid = blockIdx.x*NTHR + tid;
    const size_t WS = (size_t)HG_*H_;

    // ---------------- init + packing ----------------
    for (int i = gid; i < 3*B_*H_; i += NTOT) (&g_c[0][0][0])[i] = 0.f;
    for (int i = gid; i < 2*3*16384; i += NTOT) (&gPh[0][0][0])[i] = make_uint4(0,0,0,0);
    {
        const float* bis[6] = {ebih, ebih+HG_, ebih+2*HG_, dbih, dbih+HG_, dbih+2*HG_};
        const float* bhs[6] = {ebhh, ebhh+HG_, ebhh+2*HG_, dbhh, dbhh+HG_, dbhh+2*HG_};
        for (int i = gid; i < 6*HG_; i += NTOT){
            int s = i >> 11, n = i & (HG_-1);
            gBias[s][n] = bis[s][n] + bhs[s][n];
        }
    }
    if (gid < 256){   // seed decoder input x[:, FIN-1, 0:FOUT] -> gPp
        int mt = gid>>5, lane = gid&31, g = lane>>2, tig = lane&3;
        unsigned short hv[8], lv[8];
        #pragma unroll
        for (int ri = 0; ri < 4; ri++){
            int r24 = ri>>1, a01 = ri&1;
            #pragma unroll
            for (int half = 0; half < 2; half++){
                int k = r24*8 + 2*tig + half;
                int b = mt*16 + a01*8 + g;
                float v = (k < FOUT) ? x[(size_t)b*(FIN*T_) + (size_t)(FIN-1)*T_ + k] : 0.f;
                bsplit(v, hv[ri*2+half], lv[ri*2+half]);
            }
        }
        uint4 uh = make_uint4(packu(hv[0],hv[1]),packu(hv[2],hv[3]),packu(hv[4],hv[5]),packu(hv[6],hv[7]));
        uint4 ul = make_uint4(packu(lv[0],lv[1]),packu(lv[2],lv[3]),packu(lv[4],lv[5]),packu(lv[6],lv[7]));
        gPp[(size_t)(mt*32+lane)*2] = uh;
        gPp[(size_t)(mt*32+lane)*2+1] = ul;
    }
    for (int idx = gid; idx < T_*8*4*32; idx += NTOT){   // pack x
        int lane = idx&31, k16 = (idx>>5)&3, mt = (idx>>7)&7, t = idx>>10;
        int g = lane>>2, tig = lane&3;
        int r0 = mt*16 + g, k0 = k16*16 + 2*tig;
        const float* xa = x + (size_t)r0*(FIN*T_) + t;
        const float* xb = x + (size_t)(r0+8)*(FIN*T_) + t;
        unsigned short h[8], l[8];
        bsplit(xa[(size_t)(k0  )*T_], h[0], l[0]); bsplit(xa[(size_t)(k0+1)*T_], h[1], l[1]);
        bsplit(xb[(size_t)(k0  )*T_], h[2], l[2]); bsplit(xb[(size_t)(k0+1)*T_], h[3], l[3]);
        bsplit(xa[(size_t)(k0+8)*T_], h[4], l[4]); bsplit(xa[(size_t)(k0+9)*T_], h[5], l[5]);
        bsplit(xb[(size_t)(k0+8)*T_], h[6], l[6]); bsplit(xb[(size_t)(k0+9)*T_], h[7], l[7]);
        gXp[(size_t)idx*2]   = make_uint4(packu(h[0],h[1]),packu(h[2],h[3]),packu(h[4],h[5]),packu(h[6],h[7]));
        gXp[(size_t)idx*2+1] = make_uint4(packu(l[0],l[1]),packu(l[2],l[3]),packu(l[4],l[5]),packu(l[6],l[7]));
    }
    {   // pack weights: 6 sets, cat [Wih | Whh] along k16
        const float* W1s[6] = {eWih0, eWih, eWih+WS, dWih0, dWih, dWih+WS};
        const float* W2s[6] = {eWhh, eWhh+WS, eWhh+2*WS, dWhh, dWhh+WS, dWhh+2*WS};
        const int K1s[6] = {64,512,512,8,512,512};
        const int nk1s[6] = {4,32,32,1,32,32};
        for (int s = 0; s < 6; s++){
            const float* W1 = W1s[s]; const float* W2 = W2s[s];
            const int K1 = K1s[s], NK16 = nk1s[s]+32, nk1 = nk1s[s];
            for (int idx = gid; idx < 256*NK16*32; idx += NTOT){
                int lane = idx&31, k16 = (idx>>5)%NK16, ntile = (idx>>5)/NK16;
                int g = lane>>2, tig = lane&3;
                int n = ntile*8 + g, kb = k16*16 + 2*tig;
                float v00,v01,v10,v11;
                if (k16 < nk1){
                    v00 = (kb  <K1)? W1[(size_t)n*K1+kb]  :0.f;
                    v01 = (kb+1<K1)? W1[(size_t)n*K1+kb+1]:0.f;
                    v10 = (kb+8<K1)? W1[(size_t)n*K1+kb+8]:0.f;
                    v11 = (kb+9<K1)? W1[(size_t)n*K1+kb+9]:0.f;
                } else {
                    int k2 = kb - nk1*16;
                    v00 = W2[(size_t)n*H_+k2];   v01 = W2[(size_t)n*H_+k2+1];
                    v10 = W2[(size_t)n*H_+k2+8]; v11 = W2[(size_t)n*H_+k2+9];
                }
                unsigned short h00,l00,h01,l01,h10,l10,h11,l11;
                bsplit(v00,h00,l00); bsplit(v01,h01,l01);
                bsplit(v10,h10,l10); bsplit(v11,h11,l11);
                gWp[s][idx] = make_uint4(packu(h00,h01),packu(h10,h11),packu(l00,l01),packu(l10,l11));
            }
        }
    }
    grid_barrier();

    // ---------------- recurrent phase ----------------
    int ss = 0;
    for (int t = 0; t < T_; ++t, ++ss){
        int np = (ss&1)^1;
        layer_step(sred, tid, gXp + (size_t)t*2048, 4, &gPh[np^1][0][0],
                   gWp[0], gBias[0], 0, np, j0, bt);
        grid_barrier();
        layer_step(sred, tid, &gPh[np][0][0], 32, &gPh[np^1][1][0],
                   gWp[1], gBias[1], 1, np, j0, bt);
        grid_barrier();
        layer_step(sred, tid, &gPh[np][1][0], 32, &gPh[np^1][2][0],
                   gWp[2], gBias[2], 2, np, j0, bt);
        grid_barrier();
    }
    for (int d = 0; d < WOUT; ++d, ++ss){
        int np = (ss&1)^1;
        layer_step(sred, tid, gPp, 1, &gPh[np^1][0][0],
                   gWp[3], gBias[3], 0, np, j0, bt);
        grid_barrier();
        layer_step(sred, tid, &gPh[np][0][0], 32, &gPh[np^1][1][0],
                   gWp[4], gBias[4], 1, np, j0, bt);
        grid_barrier();
        layer_step(sred, tid, &gPh[np][1][0], 32, &gPh[np^1][2][0],
                   gWp[5], gBias[5], 2, np, j0, bt);
        grid_barrier();
        if (tid < 256){   // FC head: CTA = batch row b
            int f = tid>>5, lnn = tid&31, b = blockIdx.x;
            const float* hrow = &g_h[np][2][b][0];
            const float* wrow = fcw + f*H_;
            float ssum = 0.f;
            #pragma unroll 4
            for (int j = lnn; j < H_; j += 32) ssum += hrow[j]*wrow[j];
            #pragma unroll
            for (int o = 16; o; o >>= 1) ssum += __shfl_down_sync(0xffffffffu, ssum, o);
            if (lnn == 0){
                float v = ssum + fcb[f];
                out[(size_t)b*(FOUT*WOUT) + f*WOUT + d] = v;
                unsigned short hs, ls; bsplit(v, hs, ls);
                int mt = b>>4, gg = b&7, a01 = (b>>3)&1;
                int tg = (f>>1)&3, half = f&1;
                unsigned short* dst = (unsigned short*)
                    (gPp + ((size_t)mt*32 + (gg*4 + tg))*2);
                dst[a01*2 + half] = hs;
                dst[8 + a01*2 + half] = ls;
            }
        }
        grid_barrier();
    }
}

extern "C" void kernel_launch(void* const* d_in, const int* in_sizes, int n_in,
                              void* d_out, int out_size)
{
    lstm_persist<<<NCTA, NTHR>>>(
        (const float*)d_in[0], (const float*)d_in[1], (const float*)d_in[2],
        (const float*)d_in[3], (const float*)d_in[4], (const float*)d_in[5],
        (const float*)d_in[6], (const float*)d_in[7], (const float*)d_in[8],
        (const float*)d_in[9], (const float*)d_in[10], (const float*)d_in[11],
        (const float*)d_in[12], (float*)d_out);
}

// round 8
// speedup vs baseline: 2.7164x; 1.1797x over previous
#include <cuda_runtime.h>
#include <cuda_bf16.h>

#define B_ 128
#define H_ 512
#define HG_ 2048
#define T_ 512
#define FIN 64
#define FOUT 8
#define WOUT 64
#define NCTA 128
#define NTHR 512
#define NTOT (NCTA*NTHR)

__device__ __align__(16) uint4 gWp[6][524288];
__device__ __align__(16) uint4 gXp[1048576];
__device__ __align__(16) uint4 gPh[2][3][16384];
__device__ __align__(16) uint4 gPp[512];
__device__ float gBias[6][HG_];
__device__ float g_h[3][B_][H_];
__device__ float g_c[3][B_][H_];
__device__ unsigned g_cnt = 0;
__device__ volatile unsigned g_gen = 0;
__device__ unsigned g_cnt4[4*32];
__device__ volatile unsigned g_gen4[4*32];

__device__ __forceinline__ float sigmoidf_(float x){ return 1.f/(1.f+expf(-x)); }
__device__ __forceinline__ void bsplit(float v, unsigned short& h, unsigned short& l){
    __nv_bfloat16 bh = __float2bfloat16(v);
    __nv_bfloat16 bl = __float2bfloat16(v - __bfloat162float(bh));
    h = __bfloat16_as_ushort(bh); l = __bfloat16_as_ushort(bl);
}
__device__ __forceinline__ unsigned packu(unsigned short e, unsigned short o){
    return (unsigned)e | ((unsigned)o << 16);
}
__device__ __forceinline__ void grid_barrier(){
    __syncthreads();
    if (threadIdx.x == 0){
        __threadfence();
        unsigned gen = g_gen;
        if (atomicAdd(&g_cnt,1u) == NCTA-1){ g_cnt = 0; __threadfence(); g_gen = gen+1; }
        else { while (g_gen == gen) {} }
        __threadfence();
    }
    __syncthreads();
}
// 32-CTA group barrier: groups (bt) are data-independent after init
__device__ __forceinline__ void group_barrier(int grp){
    __syncthreads();
    if (threadIdx.x == 0){
        __threadfence();
        unsigned* cnt = &g_cnt4[grp*32];
        volatile unsigned* gen = &g_gen4[grp*32];
        unsigned gv = *gen;
        if (atomicAdd(cnt,1u) == 31){ *cnt = 0; __threadfence(); *gen = gv+1; }
        else { while (*gen == gv) {} }
        __threadfence();
    }
    __syncthreads();
}
__device__ __forceinline__ void mma_bf16(float* d, const uint4 a, unsigned b0, unsigned b1){
    asm volatile("mma.sync.aligned.m16n8k16.row.col.f32.bf16.bf16.f32 "
        "{%0,%1,%2,%3}, {%4,%5,%6,%7}, {%8,%9}, {%0,%1,%2,%3};"
        : "+f"(d[0]), "+f"(d[1]), "+f"(d[2]), "+f"(d[3])
        : "r"(a.x), "r"(a.y), "r"(a.z), "r"(a.w), "r"(b0), "r"(b1));
}

// fused layer-step; pA2 = own-layer h (read), pHw = packed h write target
__device__ __noinline__ void layer_step(
    float* sred, int tid,
    const uint4* __restrict__ pA1, int nk1,
    const uint4* __restrict__ pA2,
    const uint4* __restrict__ pW, const float* __restrict__ bias,
    int l, uint4* __restrict__ pHw, int j0, int bt)
{
    const int wid = tid>>5, lane = tid&31;
    const int kg = wid>>2, sub = wid&3, mw = sub&1, jh = sub>>1;
    const int NK16 = nk1 + 32;
    const int mtile = bt*2 + mw;
    const int g = lane>>2;

    const uint4* wp0 = pW + ((size_t)(0*64 + (j0>>3) + jh)*NK16 + kg)*32 + lane;
    const uint4* wp1 = pW + ((size_t)(1*64 + (j0>>3) + jh)*NK16 + kg)*32 + lane;
    const uint4* wp2 = pW + ((size_t)(2*64 + (j0>>3) + jh)*NK16 + kg)*32 + lane;
    const uint4* wp3 = pW + ((size_t)(3*64 + (j0>>3) + jh)*NK16 + kg)*32 + lane;

    float acc[4][4];
    #pragma unroll
    for (int q = 0; q < 4; q++){ acc[q][0]=acc[q][1]=acc[q][2]=acc[q][3]=0.f; }

    auto aptr = [&](int i) -> const uint4* {
        return (i < nk1) ? pA1 + ((size_t)(mtile*nk1 + i)*32 + lane)*2
                         : pA2 + ((size_t)(mtile*32 + (i-nk1))*32 + lane)*2;
    };

    uint4 ahi, alo, w0, w1, w2, w3;
    { const uint4* ap = aptr(kg); ahi = ap[0]; alo = ap[1];
      w0 = *wp0; w1 = *wp1; w2 = *wp2; w3 = *wp3; }

    for (int i = kg; i < NK16; i += 4){
        uint4 nahi, nalo, nw0, nw1, nw2, nw3;
        if (i + 4 < NK16){
            const uint4* ap = aptr(i+4);
            nahi = ap[0]; nalo = ap[1];
            nw0 = wp0[128]; nw1 = wp1[128]; nw2 = wp2[128]; nw3 = wp3[128];
        }
        mma_bf16(acc[0], ahi, w0.x, w0.y);
        mma_bf16(acc[1], ahi, w1.x, w1.y);
        mma_bf16(acc[2], ahi, w2.x, w2.y);
        mma_bf16(acc[3], ahi, w3.x, w3.y);
        mma_bf16(acc[0], ahi, w0.z, w0.w);
        mma_bf16(acc[1], ahi, w1.z, w1.w);
        mma_bf16(acc[2], ahi, w2.z, w2.w);
        mma_bf16(acc[3], ahi, w3.z, w3.w);
        mma_bf16(acc[0], alo, w0.x, w0.y);
        mma_bf16(acc[1], alo, w1.x, w1.y);
        mma_bf16(acc[2], alo, w2.x, w2.y);
        mma_bf16(acc[3], alo, w3.x, w3.y);
        wp0 += 128; wp1 += 128; wp2 += 128; wp3 += 128;
        ahi = nahi; alo = nalo; w0 = nw0; w1 = nw1; w2 = nw2; w3 = nw3;
    }

    __syncthreads();   // protect sred reuse across consecutive layer_steps
    {
        const int tig = lane & 3;
        float* rg = sred + kg*2304;
        #pragma unroll
        for (int q = 0; q < 4; q++){
            float* t0 = rg + (q*16 + jh*8 + 2*tig)*36 + mw*16;
            t0[g] = acc[q][0]; t0[g+8] = acc[q][2];
            t0[36+g] = acc[q][1]; t0[36+g+8] = acc[q][3];
        }
    }
    __syncthreads();

    {   // cell phase
        const int b_l = tid>>4, j_l = tid&15;
        float gate[4];
        #pragma unroll
        for (int q = 0; q < 4; q++){
            float s = 0.f;
            #pragma unroll
            for (int kk = 0; kk < 4; kk++) s += sred[kk*2304 + (q*16+j_l)*36 + b_l];
            gate[q] = s + bias[q*H_ + j0 + j_l];
        }
        const int b = bt*32 + b_l, j = j0 + j_l;
        float co = g_c[l][b][j];
        float cn = sigmoidf_(gate[1])*co + sigmoidf_(gate[0])*tanhf(gate[2]);
        g_c[l][b][j] = cn;
        float hv = sigmoidf_(gate[3])*tanhf(cn);
        g_h[l][b][j] = hv;
        unsigned short hs, ls; bsplit(hv, hs, ls);
        int mt = b>>4, rb = b&15, gg = rb&7, a01 = rb>>3;
        int k16 = j>>4, kr = j&15, tg = (kr>>1)&3, r24 = kr>>3, half = kr&1;
        int regidx = a01 + (r24<<1);
        unsigned short* dst = (unsigned short*)
            (pHw + ((size_t)(mt*32 + k16)*32 + (gg*4 + tg))*2);
        dst[regidx*2 + half] = hs;
        dst[8 + regidx*2 + half] = ls;
    }
}

__global__ __launch_bounds__(NTHR, 1) void lstm_persist(
    const float* __restrict__ x,
    const float* __restrict__ eWih0, const float* __restrict__ eWih,
    const float* __restrict__ eWhh,  const float* __restrict__ ebih,
    const float* __restrict__ ebhh,
    const float* __restrict__ dWih0, const float* __restrict__ dWih,
    const float* __restrict__ dWhh,  const float* __restrict__ dbih,
    const float* __restrict__ dbhh,
    const float* __restrict__ fcw,   const float* __restrict__ fcb,
    float* __restrict__ out)
{
    __shared__ float sred[4*2304];
    const int tid = threadIdx.x;
    const int bt = blockIdx.x >> 5;
    const int j0 = (blockIdx.x & 31)*16;
    const int grp = bt;
    const int gid = blockIdx.x*NTHR + tid;
    const size_t WS = (size_t)HG_*H_;

    // ---------------- init + packing ----------------
    for (int i = gid; i < 3*B_*H_; i += NTOT) (&g_c[0][0][0])[i] = 0.f;
    for (int i = gid; i < 2*3*16384; i += NTOT) (&gPh[0][0][0])[i] = make_uint4(0,0,0,0);
    {
        const float* bis[6] = {ebih, ebih+HG_, ebih+2*HG_, dbih, dbih+HG_, dbih+2*HG_};
        const float* bhs[6] = {ebhh, ebhh+HG_, ebhh+2*HG_, dbhh, dbhh+HG_, dbhh+2*HG_};
        for (int i = gid; i < 6*HG_; i += NTOT){
            int s = i >> 11, n = i & (HG_-1);
            gBias[s][n] = bis[s][n] + bhs[s][n];
        }
    }
    if (gid < 256){   // seed decoder input
        int mt = gid>>5, lane = gid&31, g = lane>>2, tig = lane&3;
        unsigned short hv[8], lv[8];
        #pragma unroll
        for (int ri = 0; ri < 4; ri++){
            int r24 = ri>>1, a01 = ri&1;
            #pragma unroll
            for (int half = 0; half < 2; half++){
                int k = r24*8 + 2*tig + half;
                int b = mt*16 + a01*8 + g;
                float v = (k < FOUT) ? x[(size_t)b*(FIN*T_) + (size_t)(FIN-1)*T_ + k] : 0.f;
                bsplit(v, hv[ri*2+half], lv[ri*2+half]);
            }
        }
        gPp[(size_t)(mt*32+lane)*2]   = make_uint4(packu(hv[0],hv[1]),packu(hv[2],hv[3]),packu(hv[4],hv[5]),packu(hv[6],hv[7]));
        gPp[(size_t)(mt*32+lane)*2+1] = make_uint4(packu(lv[0],lv[1]),packu(lv[2],lv[3]),packu(lv[4],lv[5]),packu(lv[6],lv[7]));
    }
    for (int idx = gid; idx < T_*8*4*32; idx += NTOT){   // pack x
        int lane = idx&31, k16 = (idx>>5)&3, mt = (idx>>7)&7, t = idx>>10;
        int g = lane>>2, tig = lane&3;
        int r0 = mt*16 + g, k0 = k16*16 + 2*tig;
        const float* xa = x + (size_t)r0*(FIN*T_) + t;
        const float* xb = x + (size_t)(r0+8)*(FIN*T_) + t;
        unsigned short h[8], l[8];
        bsplit(xa[(size_t)(k0  )*T_], h[0], l[0]); bsplit(xa[(size_t)(k0+1)*T_], h[1], l[1]);
        bsplit(xb[(size_t)(k0  )*T_], h[2], l[2]); bsplit(xb[(size_t)(k0+1)*T_], h[3], l[3]);
        bsplit(xa[(size_t)(k0+8)*T_], h[4], l[4]); bsplit(xa[(size_t)(k0+9)*T_], h[5], l[5]);
        bsplit(xb[(size_t)(k0+8)*T_], h[6], l[6]); bsplit(xb[(size_t)(k0+9)*T_], h[7], l[7]);
        gXp[(size_t)idx*2]   = make_uint4(packu(h[0],h[1]),packu(h[2],h[3]),packu(h[4],h[5]),packu(h[6],h[7]));
        gXp[(size_t)idx*2+1] = make_uint4(packu(l[0],l[1]),packu(l[2],l[3]),packu(l[4],l[5]),packu(l[6],l[7]));
    }
    {   // pack weights
        const float* W1s[6] = {eWih0, eWih, eWih+WS, dWih0, dWih, dWih+WS};
        const float* W2s[6] = {eWhh, eWhh+WS, eWhh+2*WS, dWhh, dWhh+WS, dWhh+2*WS};
        const int K1s[6] = {64,512,512,8,512,512};
        const int nk1s[6] = {4,32,32,1,32,32};
        for (int s = 0; s < 6; s++){
            const float* W1 = W1s[s]; const float* W2 = W2s[s];
            const int K1 = K1s[s], NK16 = nk1s[s]+32, nk1 = nk1s[s];
            for (int idx = gid; idx < 256*NK16*32; idx += NTOT){
                int lane = idx&31, k16 = (idx>>5)%NK16, ntile = (idx>>5)/NK16;
                int g = lane>>2, tig = lane&3;
                int n = ntile*8 + g, kb = k16*16 + 2*tig;
                float v00,v01,v10,v11;
                if (k16 < nk1){
                    v00 = (kb  <K1)? W1[(size_t)n*K1+kb]  :0.f;
                    v01 = (kb+1<K1)? W1[(size_t)n*K1+kb+1]:0.f;
                    v10 = (kb+8<K1)? W1[(size_t)n*K1+kb+8]:0.f;
                    v11 = (kb+9<K1)? W1[(size_t)n*K1+kb+9]:0.f;
                } else {
                    int k2 = kb - nk1*16;
                    v00 = W2[(size_t)n*H_+k2];   v01 = W2[(size_t)n*H_+k2+1];
                    v10 = W2[(size_t)n*H_+k2+8]; v11 = W2[(size_t)n*H_+k2+9];
                }
                unsigned short h00,l00,h01,l01,h10,l10,h11,l11;
                bsplit(v00,h00,l00); bsplit(v01,h01,l01);
                bsplit(v10,h10,l10); bsplit(v11,h11,l11);
                gWp[s][idx] = make_uint4(packu(h00,h01),packu(h10,h11),packu(l00,l01),packu(l10,l11));
            }
        }
    }
    grid_barrier();

    // ---------------- encoder: layer wavefront, 1 barrier / super-step ----
    int rp0 = 0, rp1 = 0, rp2 = 0;   // last-written parity per layer
    for (int s = 0; s < T_ + 2; ++s){
        int r0 = rp0, r1 = rp1, r2 = rp2;
        if (s < T_){
            layer_step(sred, tid, gXp+(size_t)s*2048, 4, &gPh[r0][0][0],
                       gWp[0], gBias[0], 0, &gPh[r0^1][0][0], j0, bt);
            rp0 ^= 1;
        }
        if (s >= 1 && s < T_ + 1){
            layer_step(sred, tid, &gPh[r0][0][0], 32, &gPh[r1][1][0],
                       gWp[1], gBias[1], 1, &gPh[r1^1][1][0], j0, bt);
            rp1 ^= 1;
        }
        if (s >= 2){
            layer_step(sred, tid, &gPh[r1][1][0], 32, &gPh[r2][2][0],
                       gWp[2], gBias[2], 2, &gPh[r2^1][2][0], j0, bt);
            rp2 ^= 1;
        }
        group_barrier(grp);
    }

    // ---------------- decoder: serial 4-phase loop ----------------
    for (int d = 0; d < WOUT; ++d){
        layer_step(sred, tid, gPp, 1, &gPh[rp0][0][0],
                   gWp[3], gBias[3], 0, &gPh[rp0^1][0][0], j0, bt);
        rp0 ^= 1; group_barrier(grp);
        layer_step(sred, tid, &gPh[rp0][0][0], 32, &gPh[rp1][1][0],
                   gWp[4], gBias[4], 1, &gPh[rp1^1][1][0], j0, bt);
        rp1 ^= 1; group_barrier(grp);
        layer_step(sred, tid, &gPh[rp1][1][0], 32, &gPh[rp2][2][0],
                   gWp[5], gBias[5], 2, &gPh[rp2^1][2][0], j0, bt);
        rp2 ^= 1; group_barrier(grp);
        if (tid < 256){   // FC head: CTA = batch row b (same bt group)
            int f = tid>>5, lnn = tid&31, b = blockIdx.x;
            const float* hrow = &g_h[2][b][0];
            const float* wrow = fcw + f*H_;
            float ssum = 0.f;
            #pragma unroll 4
            for (int j = lnn; j < H_; j += 32) ssum += hrow[j]*wrow[j];
            #pragma unroll
            for (int o = 16; o; o >>= 1) ssum += __shfl_down_sync(0xffffffffu, ssum, o);
            if (lnn == 0){
                float v = ssum + fcb[f];
                out[(size_t)b*(FOUT*WOUT) + f*WOUT + d] = v;
                unsigned short hs, ls; bsplit(v, hs, ls);
                int mt = b>>4, gg = b&7, a01 = (b>>3)&1;
                int tg = (f>>1)&3, half = f&1;
                unsigned short* dst = (unsigned short*)
                    (gPp + ((size_t)mt*32 + (gg*4 + tg))*2);
                dst[a01*2 + half] = hs;
                dst[8 + a01*2 + half] = ls;
            }
        }
        group_barrier(grp);
    }
}

extern "C" void kernel_launch(void* const* d_in, const int* in_sizes, int n_in,
                              void* d_out, int out_size)
{
    lstm_persist<<<NCTA, NTHR>>>(
        (const float*)d_in[0], (const float*)d_in[1], (const float*)d_in[2],
        (const float*)d_in[3], (const float*)d_in[4], (const float*)d_in[5],
        (const float*)d_in[6], (const float*)d_in[7], (const float*)d_in[8],
        (const float*)d_in[9], (const float*)d_in[10], (const float*)d_in[11],
        (const float*)d_in[12], (float*)d_out);
}